// round 15
// baseline (speedup 1.0000x reference)
#include <cuda_runtime.h>
#include <cuda_fp16.h>
#include <cstdint>

#define Bv  2
#define Sv  2048
#define Dv  512
#define Hv  8
#define HDv 64
#define BH  16

// Scratch (allocation-free __device__ globals)
__device__ uint32_t g_xf[4096*256];                     // x fp16 pairs along D
__device__ uint32_t g_wf[3*512*256];                    // (64*w) fp16 pairs
__device__ uint32_t g_qh[BH*Sv*32];                     // (Q/16) fp16 pairs along HD
__device__ uint32_t g_kh[BH*Sv*32];                     // K fp16 pairs along HD
__device__ uint32_t g_vt[BH*HDv*(Sv/2)];                // Vt fp16 pairs along S

// ---------------------------------------------------------------------------
// helpers
// ---------------------------------------------------------------------------
__device__ __forceinline__ uint32_t smem_u32(const void* p) {
    uint32_t a;
    asm("{ .reg .u64 t; cvta.to.shared.u64 t, %1; cvt.u32.u64 %0, t; }"
        : "=r"(a) : "l"(p));
    return a;
}
__device__ __forceinline__ void cp16(uint32_t dst, const void* src) {
    asm volatile("cp.async.cg.shared.global [%0], [%1], 16;" :: "r"(dst), "l"(src) : "memory");
}
__device__ __forceinline__ void cp_commit() { asm volatile("cp.async.commit_group;" ::: "memory"); }
template<int N>
__device__ __forceinline__ void cp_wait() { asm volatile("cp.async.wait_group %0;" :: "n"(N) : "memory"); }

__device__ __forceinline__ void ldsm4(uint32_t* r, uint32_t addr) {
    asm volatile("ldmatrix.sync.aligned.m8n8.x4.shared.b16 {%0,%1,%2,%3}, [%4];"
                 : "=r"(r[0]), "=r"(r[1]), "=r"(r[2]), "=r"(r[3]) : "r"(addr));
}

// fp16 m16n8k16, scalar b operands
__device__ __forceinline__ void mma16f(float* d, const uint32_t* a, uint32_t b0, uint32_t b1) {
    asm volatile(
        "mma.sync.aligned.m16n8k16.row.col.f32.f16.f16.f32 "
        "{%0,%1,%2,%3}, {%4,%5,%6,%7}, {%8,%9}, {%0,%1,%2,%3};"
        : "+f"(d[0]), "+f"(d[1]), "+f"(d[2]), "+f"(d[3])
        : "r"(a[0]), "r"(a[1]), "r"(a[2]), "r"(a[3]), "r"(b0), "r"(b1));
}

__device__ __forceinline__ uint32_t pack_f16(float f0, float f1) {
    uint32_t h;
    asm("cvt.rn.f16x2.f32 %0, %1, %2;" : "=r"(h) : "f"(f1), "f"(f0));
    return h;
}

// sigmoid of a pair via tanh.approx.f16x2 (accumulators already = z/2):
//   sigmoid(z) = 0.5*tanh(z/2) + 0.5
__device__ __forceinline__ uint32_t sigt(float f0, float f1) {
    uint32_t p = pack_f16(f0, f1);
    uint32_t t, r;
    asm("tanh.approx.f16x2 %0, %1;" : "=r"(t) : "r"(p));
    const uint32_t hlf = 0x38003800u;   // (0.5, 0.5) fp16x2
    asm("fma.rn.f16x2 %0, %1, %2, %3;" : "=r"(r) : "r"(t), "r"(hlf), "r"(hlf));
    return r;
}

// u32 tile stage: R rows x C u32 cols, smem row stride ST u32, gmem stride ld u32
template<int R, int C, int ST, int NT>
__device__ __forceinline__ void stage_u(uint32_t dst, const uint32_t* src, int ld) {
    constexpr int G = C / 4;
    #pragma unroll
    for (int u = 0; u < (R * G) / NT; u++) {
        const int e = u * NT + threadIdx.x;
        const int r = e / G, g = e % G;
        cp16(dst + (uint32_t)(r * ST + g * 4) * 4, src + (size_t)r * ld + g * 4);
    }
}

// ---------------------------------------------------------------------------
// Kernel 0: x -> fp16 pairs;  w*64 -> fp16 pairs.  2x float4 per thread.
// ---------------------------------------------------------------------------
__global__ __launch_bounds__(256) void prep_xw(
    const float* __restrict__ x,  const float* __restrict__ wq,
    const float* __restrict__ wk, const float* __restrict__ wv)
{
    const uint32_t XN4 = 4096u * 128u;
    const uint32_t WN4 = 512u * 128u;
    const uint32_t HALF = XN4 + 3u * WN4 >> 1;   // 360448
    #pragma unroll
    for (int u = 0; u < 2; u++) {
        const uint32_t i = blockIdx.x * 256u + threadIdx.x + (uint32_t)u * HALF;
        if (i < XN4) {
            float4 f = ((const float4*)x)[i];
            uint2 o = make_uint2(pack_f16(f.x, f.y), pack_f16(f.z, f.w));
            ((uint2*)g_xf)[i] = o;
        } else {
            const uint32_t j = i - XN4;
            const float* w = (j < WN4) ? wq : (j < 2u*WN4) ? wk : wv;
            float4 f = ((const float4*)w)[j % WN4];
            uint2 o = make_uint2(pack_f16(f.x * 64.0f, f.y * 64.0f),
                                 pack_f16(f.z * 64.0f, f.w * 64.0f));
            ((uint2*)g_wf)[j] = o;
        }
    }
}

// ---------------------------------------------------------------------------
// Kernel 1: QKV projection (unchanged from round 14).
// ---------------------------------------------------------------------------
__global__ __launch_bounds__(256, 3) void proj_mma(
    const float* __restrict__ bq, const float* __restrict__ bk,
    const float* __restrict__ bv)
{
    extern __shared__ uint32_t su[];
    const uint32_t sb = smem_u32(su);
    const int tid = threadIdx.x, wid = tid >> 5, lane = tid & 31;
    const int g = lane >> 2, tg = lane & 3;
    const int lrow = lane & 15;
    const uint32_t lhi = (uint32_t)(lane >> 4) * 16u;
    const int wm = (wid >> 2) * 32, wn = (wid & 3) * 32;
    const int m0 = blockIdx.x * 64, n0 = blockIdx.y * 128;
    const int z  = blockIdx.z;
    const float* bias = (z == 0) ? bq : (z == 1) ? bk : bv;

    const uint32_t* Xf_g = g_xf + (size_t)m0 * 256;
    const uint32_t* Wf_g = g_wf + ((size_t)z * 512 + n0) * 256;

    const uint32_t ax  = sb + (uint32_t)((wm + lrow) * 36) * 4 + lhi;
    const uint32_t awf = sb + 2304u*4u + (uint32_t)((wn + lrow) * 36) * 4 + lhi;

    float acc[2][4][4] = {};

    stage_u<64, 32,36,256>(sb,           Xf_g, 256);
    stage_u<128,32,36,256>(sb + 2304*4,  Wf_g, 256);
    cp_commit();
    cp_wait<0>();
    __syncthreads();

    #pragma unroll 1
    for (int kc = 0; kc < 8; kc++) {
        if (kc + 1 < 8) {
            const uint32_t bo = ((kc + 1) & 1) * 6912u * 4u;
            const int co = (kc + 1) * 32;
            stage_u<64, 32,36,256>(sb + bo,           Xf_g + co, 256);
            stage_u<128,32,36,256>(sb + bo + 2304*4,  Wf_g + co, 256);
            cp_commit();
        }
        const uint32_t bo = (kc & 1) * 6912u * 4u;

        #pragma unroll
        for (int ks = 0; ks < 4; ks++) {
            const uint32_t ko = (uint32_t)ks * 32u;
            uint32_t af[2][4], wfr[2][4];
            #pragma unroll
            for (int i = 0; i < 2; i++)
                ldsm4(af[i], ax + bo + (uint32_t)i * (16*144) + ko);
            #pragma unroll
            for (int jh = 0; jh < 2; jh++)
                ldsm4(wfr[jh], awf + bo + (uint32_t)jh * (16*144) + ko);
            #pragma unroll
            for (int i = 0; i < 2; i++)
                #pragma unroll
                for (int j = 0; j < 4; j++) {
                    const int jh = j >> 1, sel = j & 1;
                    mma16f(acc[i][j], af[i], wfr[jh][sel], wfr[jh][sel + 2]);
                }
        }
        if (kc + 1 < 8) {
            cp_wait<0>();
            __syncthreads();
        }
    }

    if (z != 2) {
        const float post = (z == 0) ? 0.0625f : 1.0f;
        uint32_t* o = (z == 0) ? g_qh : g_kh;
        #pragma unroll
        for (int i = 0; i < 2; i++)
            #pragma unroll
            for (int j = 0; j < 4; j++) {
                const int c  = n0 + wn + j*8 + 2*tg;
                const int h  = c >> 6, hd = c & 63;
                const float b0 = bias[c], b1 = bias[c + 1];
                #pragma unroll
                for (int rr = 0; rr < 2; rr++) {
                    const int m  = m0 + wm + i*16 + g + rr*8;
                    const int b_ = m >> 11, s = m & 2047;
                    const float f0 = (acc[i][j][rr*2+0] * 0.015625f + b0) * post;
                    const float f1 = (acc[i][j][rr*2+1] * 0.015625f + b1) * post;
                    o[(((size_t)(b_ * Hv + h)) * Sv + s) * 32 + (hd >> 1)] = pack_f16(f0, f1);
                }
            }
    } else {
        float* smf = (float*)su;       // [128 cols][66] floats
        __syncthreads();
        #pragma unroll
        for (int i = 0; i < 2; i++)
            #pragma unroll
            for (int j = 0; j < 4; j++) {
                const int hl = wn + j*8 + 2*tg;
                const int c  = n0 + hl;
                const float b0 = bias[c], b1 = bias[c + 1];
                #pragma unroll
                for (int rr = 0; rr < 2; rr++) {
                    const int ml = wm + i*16 + g + rr*8;
                    smf[hl * 66 + ml]       = acc[i][j][rr*2+0] * 0.015625f + b0;
                    smf[(hl + 1) * 66 + ml] = acc[i][j][rr*2+1] * 0.015625f + b1;
                }
            }
        __syncthreads();
        const int b_ = m0 >> 11, s0 = m0 & 2047;
        #pragma unroll
        for (int u = 0; u < 16; u++) {
            const int o  = u * 256 + tid;
            const int hl = o >> 5;
            const int sp = o & 31;
            const int head = (n0 + hl) >> 6, hd = (n0 + hl) & 63;
            g_vt[(((size_t)(b_ * Hv + head)) * HDv + hd) * (Sv/2) + (s0 >> 1) + sp] =
                pack_f16(smf[hl * 66 + 2*sp], smf[hl * 66 + 2*sp + 1]);
        }
    }
}

// ---------------------------------------------------------------------------
// Kernel 2: fused sigmoid attention, SOFTWARE-PIPELINED on pa:
//   body(t): prefetch(t+1) -> GEMM2(pa[t-1], V[t-1]) -> GEMM1(t) -> sigt(t)
// GEMM2 and GEMM1 in one body are independent MMA streams; sigt latency is
// consumed one iteration later, off the critical path.
// 128 thr, 4 warps = 2 row-groups x 2 KV-halves, 4 blocks/SM.
// smem u32: Qh 0 (2304), Kh 2304 + kb*2304 (2 bufs), Vt 6912 + vb*2304 (3 bufs).
// Total 13824 u32 = 55296 B; 4 x 55296 = 221184 B/SM.
// ---------------------------------------------------------------------------
__global__ __launch_bounds__(128, 4) void attn_mma(float* __restrict__ out)
{
    extern __shared__ uint32_t su[];
    const uint32_t sb = smem_u32(su);
    const int tid = threadIdx.x, wid = tid >> 5, lane = tid & 31;
    const int g = lane >> 2, tg = lane & 3;
    const int lrow = lane & 15;
    const uint32_t lhi = (uint32_t)(lane >> 4) * 16u;
    const int wm = (wid >> 1) * 32;      // row group (0 or 32)
    const int wc = wid & 1;              // KV half
    const int qt = blockIdx.x, bh = blockIdx.y;

    const uint32_t* Qhg = g_qh + ((size_t)bh * Sv + (size_t)qt * 64) * 32;
    const uint32_t* Khg = g_kh + (size_t)bh * Sv * 32;
    const uint32_t* Vtg = g_vt + (size_t)bh * HDv * (Sv/2);

    float acc2[2][8][4] = {};

    stage_u<64,32,36,128>(sb,           Qhg, 32);   // Q
    stage_u<64,32,36,128>(sb + 2304*4,  Khg, 32);   // K(0) -> kbuf0
    stage_u<64,32,36,128>(sb + 6912*4,  Vtg, Sv/2); // V(0) -> vbuf0
    cp_commit();
    cp_wait<0>();
    __syncthreads();

    const uint32_t qaddr = sb + (uint32_t)((wm + lrow) * 36) * 4 + lhi;
    const uint32_t kaddr = sb + 2304u*4u + (uint32_t)((wc*32 + lrow) * 36) * 4 + lhi;
    const uint32_t vlane = sb + 6912u*4u + (uint32_t)(lrow * 36) * 4
                         + (uint32_t)wc * 64u + lhi;

    // V triple-buffer indices: prev (GEMM2 source), cur (this tile), next (prefetch)
    int ivp = 2, ivc = 0, ivn = 1;
    uint32_t pa[2][2][4];              // [kc][i] — pipelined across iterations

    const int NT = Sv / 64;   // 32
    #pragma unroll 1
    for (int t = 0; t < NT; t++) {
        if (t + 1 < NT) {
            const uint32_t bk = ((t + 1) & 1) * 2304u * 4u;
            stage_u<64,32,36,128>(sb + 2304*4 + bk, Khg + (size_t)(t+1) * 64 * 32, 32);
            stage_u<64,32,36,128>(sb + 6912*4 + (uint32_t)ivn * (2304u*4u),
                                  Vtg + (size_t)(t+1) * 32, Sv/2);
            cp_commit();
        }

        // ---- GEMM2 for tile t-1 (independent of this tile's GEMM1 stream)
        if (t > 0) {
            const uint32_t vb_t = vlane + (uint32_t)ivp * (2304u*4u);
            #pragma unroll
            for (int kc = 0; kc < 2; kc++)
                #pragma unroll
                for (int vq = 0; vq < 4; vq++) {
                    uint32_t vb[4];
                    ldsm4(vb, vb_t + (uint32_t)(vq * 16 * 144) + (uint32_t)kc * 32u);
                    #pragma unroll
                    for (int i = 0; i < 2; i++) {
                        mma16f(acc2[i][vq*2+0], pa[kc][i], vb[0], vb[2]);
                        mma16f(acc2[i][vq*2+1], pa[kc][i], vb[1], vb[3]);
                    }
                }
        }

        // ---- GEMM1 tile t
        const uint32_t kb_t = kaddr + (uint32_t)(t & 1) * (2304u*4u);
        float acc1[2][2][2][4] = {};   // [kc][i][j]
        #pragma unroll
        for (int ks = 0; ks < 4; ks++) {
            const uint32_t ko = (uint32_t)ks * 32u;
            uint32_t qa[2][4], kb0[4], kb1[4];
            #pragma unroll
            for (int i = 0; i < 2; i++)
                ldsm4(qa[i], qaddr + (uint32_t)i * (16*144) + ko);
            ldsm4(kb0, kb_t + ko);
            ldsm4(kb1, kb_t + (16*144) + ko);
            #pragma unroll
            for (int i = 0; i < 2; i++) {
                mma16f(acc1[0][i][0], qa[i], kb0[0], kb0[2]);
                mma16f(acc1[0][i][1], qa[i], kb0[1], kb0[3]);
                mma16f(acc1[1][i][0], qa[i], kb1[0], kb1[2]);
                mma16f(acc1[1][i][1], qa[i], kb1[1], kb1[3]);
            }
        }

        // ---- sigt(t): result consumed next iteration
        #pragma unroll
        for (int kc = 0; kc < 2; kc++)
            #pragma unroll
            for (int i = 0; i < 2; i++) {
                pa[kc][i][0] = sigt(acc1[kc][i][0][0], acc1[kc][i][0][1]);
                pa[kc][i][1] = sigt(acc1[kc][i][0][2], acc1[kc][i][0][3]);
                pa[kc][i][2] = sigt(acc1[kc][i][1][0], acc1[kc][i][1][1]);
                pa[kc][i][3] = sigt(acc1[kc][i][1][2], acc1[kc][i][1][3]);
            }

        // rotate V buffers
        { const int tmp = ivp; ivp = ivc; ivc = ivn; ivn = tmp; }

        if (t + 1 < NT) {
            cp_wait<0>();
            __syncthreads();
        }
    }

    // ---- drain: GEMM2 for the last tile (V(NT-1) is at index ivp after rotation)
    {
        const uint32_t vb_t = vlane + (uint32_t)ivp * (2304u*4u);
        #pragma unroll
        for (int kc = 0; kc < 2; kc++)
            #pragma unroll
            for (int vq = 0; vq < 4; vq++) {
                uint32_t vb[4];
                ldsm4(vb, vb_t + (uint32_t)(vq * 16 * 144) + (uint32_t)kc * 32u);
                #pragma unroll
                for (int i = 0; i < 2; i++) {
                    mma16f(acc2[i][vq*2+0], pa[kc][i], vb[0], vb[2]);
                    mma16f(acc2[i][vq*2+1], pa[kc][i], vb[1], vb[3]);
                }
            }
    }

    // ---- 2-way cross-warp O reduction (smem reuses dead operand tiles)
    float* smf = (float*)su;                   // 64 x 68 floats = 4352 < 13824
    __syncthreads();
    if (wc == 1) {
        #pragma unroll
        for (int i = 0; i < 2; i++)
            #pragma unroll
            for (int j2 = 0; j2 < 8; j2++)
                #pragma unroll
                for (int rr = 0; rr < 2; rr++) {
                    const int r = wm + i*16 + g + rr*8;
                    *(float2*)&smf[r * 68 + j2*8 + 2*tg] =
                        make_float2(acc2[i][j2][rr*2+0], acc2[i][j2][rr*2+1]);
                }
    }
    __syncthreads();
    if (wc == 0) {
        const int b_ = bh >> 3, h = bh & 7;
        #pragma unroll
        for (int i = 0; i < 2; i++)
            #pragma unroll
            for (int j2 = 0; j2 < 8; j2++)
                #pragma unroll
                for (int rr = 0; rr < 2; rr++) {
                    const int r = wm + i*16 + g + rr*8;
                    float2 v = *(const float2*)&smf[r * 68 + j2*8 + 2*tg];
                    v.x += acc2[i][j2][rr*2+0];
                    v.y += acc2[i][j2][rr*2+1];
                    const int s = qt * 64 + r;
                    *(float2*)&out[((size_t)(b_ * Sv + s)) * Dv + h * HDv + j2*8 + 2*tg] = v;
                }
    }
}

// ---------------------------------------------------------------------------
extern "C" void kernel_launch(void* const* d_in, const int* in_sizes, int n_in,
                              void* d_out, int out_size)
{
    const float* x  = (const float*)d_in[0];
    const float* wq = (const float*)d_in[1];
    const float* bq = (const float*)d_in[2];
    const float* wk = (const float*)d_in[3];
    const float* bk = (const float*)d_in[4];
    const float* wv = (const float*)d_in[5];
    const float* bv = (const float*)d_in[6];
    float* out = (float*)d_out;

    const int proj_smem = 13824 * 4;    // 55296 B
    const int attn_smem = 13824 * 4;    // 55296 B
    cudaFuncSetAttribute(proj_mma, cudaFuncAttributeMaxDynamicSharedMemorySize, proj_smem);
    cudaFuncSetAttribute(attn_mma, cudaFuncAttributeMaxDynamicSharedMemorySize, attn_smem);

    prep_xw<<<1408, 256>>>(x, wq, wk, wv);

    dim3 g1((Bv * Sv) / 64, Dv / 128, 3);
    proj_mma<<<g1, 256, proj_smem>>>(bq, bk, bv);

    dim3 g3(Sv / 64, BH);
    attn_mma<<<g3, 128, attn_smem>>>(out);
}

// round 16
// speedup vs baseline: 1.0140x; 1.0140x over previous
#include <cuda_runtime.h>
#include <cuda_fp16.h>
#include <cstdint>

#define Bv  2
#define Sv  2048
#define Dv  512
#define Hv  8
#define HDv 64
#define BH  16

// Scratch (allocation-free __device__ globals)
__device__ uint32_t g_xf[4096*256];                     // x fp16 pairs along D
__device__ uint32_t g_wf[3*512*256];                    // (64*w) fp16 pairs
__device__ uint32_t g_qh[BH*Sv*32];                     // (Q/16) fp16 pairs along HD
__device__ uint32_t g_kh[BH*Sv*32];                     // K fp16 pairs along HD
__device__ uint32_t g_vt[BH*HDv*(Sv/2)];                // Vt fp16 pairs along S

// ---------------------------------------------------------------------------
// helpers
// ---------------------------------------------------------------------------
__device__ __forceinline__ uint32_t smem_u32(const void* p) {
    uint32_t a;
    asm("{ .reg .u64 t; cvta.to.shared.u64 t, %1; cvt.u32.u64 %0, t; }"
        : "=r"(a) : "l"(p));
    return a;
}
__device__ __forceinline__ void cp16(uint32_t dst, const void* src) {
    asm volatile("cp.async.cg.shared.global [%0], [%1], 16;" :: "r"(dst), "l"(src) : "memory");
}
__device__ __forceinline__ void cp_commit() { asm volatile("cp.async.commit_group;" ::: "memory"); }
template<int N>
__device__ __forceinline__ void cp_wait() { asm volatile("cp.async.wait_group %0;" :: "n"(N) : "memory"); }

__device__ __forceinline__ void ldsm4(uint32_t* r, uint32_t addr) {
    asm volatile("ldmatrix.sync.aligned.m8n8.x4.shared.b16 {%0,%1,%2,%3}, [%4];"
                 : "=r"(r[0]), "=r"(r[1]), "=r"(r[2]), "=r"(r[3]) : "r"(addr));
}

// fp16 m16n8k16, scalar b operands
__device__ __forceinline__ void mma16f(float* d, const uint32_t* a, uint32_t b0, uint32_t b1) {
    asm volatile(
        "mma.sync.aligned.m16n8k16.row.col.f32.f16.f16.f32 "
        "{%0,%1,%2,%3}, {%4,%5,%6,%7}, {%8,%9}, {%0,%1,%2,%3};"
        : "+f"(d[0]), "+f"(d[1]), "+f"(d[2]), "+f"(d[3])
        : "r"(a[0]), "r"(a[1]), "r"(a[2]), "r"(a[3]), "r"(b0), "r"(b1));
}

__device__ __forceinline__ uint32_t pack_f16(float f0, float f1) {
    uint32_t h;
    asm("cvt.rn.f16x2.f32 %0, %1, %2;" : "=r"(h) : "f"(f1), "f"(f0));
    return h;
}

// sigmoid of a pair via tanh.approx.f16x2 (accumulators already = z/2):
//   sigmoid(z) = 0.5*tanh(z/2) + 0.5
__device__ __forceinline__ uint32_t sigt(float f0, float f1) {
    uint32_t p = pack_f16(f0, f1);
    uint32_t t, r;
    asm("tanh.approx.f16x2 %0, %1;" : "=r"(t) : "r"(p));
    const uint32_t hlf = 0x38003800u;   // (0.5, 0.5) fp16x2
    asm("fma.rn.f16x2 %0, %1, %2, %3;" : "=r"(r) : "r"(t), "r"(hlf), "r"(hlf));
    return r;
}

// u32 tile stage: R rows x C u32 cols, smem row stride ST u32, gmem stride ld u32
template<int R, int C, int ST, int NT>
__device__ __forceinline__ void stage_u(uint32_t dst, const uint32_t* src, int ld) {
    constexpr int G = C / 4;
    #pragma unroll
    for (int u = 0; u < (R * G) / NT; u++) {
        const int e = u * NT + threadIdx.x;
        const int r = e / G, g = e % G;
        cp16(dst + (uint32_t)(r * ST + g * 4) * 4, src + (size_t)r * ld + g * 4);
    }
}

// ---------------------------------------------------------------------------
// Kernel 0: x -> fp16 pairs;  w*64 -> fp16 pairs.  4x float4 per thread.
// ---------------------------------------------------------------------------
__global__ __launch_bounds__(256) void prep_xw(
    const float* __restrict__ x,  const float* __restrict__ wq,
    const float* __restrict__ wk, const float* __restrict__ wv)
{
    const uint32_t XN4 = 4096u * 128u;          // 524288
    const uint32_t WN4 = 512u * 128u;           // 65536
    const uint32_t QTR = (XN4 + 3u * WN4) / 4u; // 180224
    #pragma unroll
    for (int u = 0; u < 4; u++) {
        const uint32_t i = blockIdx.x * 256u + threadIdx.x + (uint32_t)u * QTR;
        if (i < XN4) {
            float4 f = ((const float4*)x)[i];
            uint2 o = make_uint2(pack_f16(f.x, f.y), pack_f16(f.z, f.w));
            ((uint2*)g_xf)[i] = o;
        } else {
            const uint32_t j = i - XN4;
            const float* w = (j < WN4) ? wq : (j < 2u*WN4) ? wk : wv;
            float4 f = ((const float4*)w)[j % WN4];
            uint2 o = make_uint2(pack_f16(f.x * 64.0f, f.y * 64.0f),
                                 pack_f16(f.z * 64.0f, f.w * 64.0f));
            ((uint2*)g_wf)[j] = o;
        }
    }
}

// ---------------------------------------------------------------------------
// Kernel 1: QKV projection, single-term fp16: X_f16 . (64W)_f16, epilogue /64.
// Q additionally pre-scaled by 1/16 (tanh half-angle).
// 128x128 block tile (halves L2 operand traffic vs 64x128): 256 thr,
// 8 warps (2x4), warp 64x32.  K-tile = 32 u32 (64 fp16), 8 tiles, dbl-buffered.
// 2 blocks/SM.  smem u32 (stride 36): per buffer Xf 0 (4608), Wf 4608 (4608);
// buffer stride 9216.  Total 18432 u32 = 73728 B.
// V epilogue: smem transpose [128][130] fp32 -> g_vt fp16 pairs along S.
// ---------------------------------------------------------------------------
__global__ __launch_bounds__(256, 2) void proj_mma(
    const float* __restrict__ bq, const float* __restrict__ bk,
    const float* __restrict__ bv)
{
    extern __shared__ uint32_t su[];
    const uint32_t sb = smem_u32(su);
    const int tid = threadIdx.x, wid = tid >> 5, lane = tid & 31;
    const int g = lane >> 2, tg = lane & 3;
    const int lrow = lane & 15;
    const uint32_t lhi = (uint32_t)(lane >> 4) * 16u;
    const int wm = (wid >> 2) * 64, wn = (wid & 3) * 32;
    const int m0 = blockIdx.x * 128, n0 = blockIdx.y * 128;
    const int z  = blockIdx.z;
    const float* bias = (z == 0) ? bq : (z == 1) ? bk : bv;

    const uint32_t* Xf_g = g_xf + (size_t)m0 * 256;
    const uint32_t* Wf_g = g_wf + ((size_t)z * 512 + n0) * 256;

    const uint32_t ax  = sb + (uint32_t)((wm + lrow) * 36) * 4 + lhi;
    const uint32_t awf = sb + 4608u*4u + (uint32_t)((wn + lrow) * 36) * 4 + lhi;

    float acc[4][4][4] = {};

    stage_u<128,32,36,256>(sb,           Xf_g, 256);
    stage_u<128,32,36,256>(sb + 4608*4,  Wf_g, 256);
    cp_commit();
    cp_wait<0>();
    __syncthreads();

    #pragma unroll 1
    for (int kc = 0; kc < 8; kc++) {
        if (kc + 1 < 8) {
            const uint32_t bo = ((kc + 1) & 1) * 9216u * 4u;
            const int co = (kc + 1) * 32;
            stage_u<128,32,36,256>(sb + bo,           Xf_g + co, 256);
            stage_u<128,32,36,256>(sb + bo + 4608*4,  Wf_g + co, 256);
            cp_commit();
        }
        const uint32_t bo = (kc & 1) * 9216u * 4u;

        #pragma unroll
        for (int ks = 0; ks < 4; ks++) {
            const uint32_t ko = (uint32_t)ks * 32u;
            uint32_t af[4][4], wfr[2][4];
            #pragma unroll
            for (int i = 0; i < 4; i++)
                ldsm4(af[i], ax + bo + (uint32_t)i * (16*144) + ko);
            #pragma unroll
            for (int jh = 0; jh < 2; jh++)
                ldsm4(wfr[jh], awf + bo + (uint32_t)jh * (16*144) + ko);
            #pragma unroll
            for (int i = 0; i < 4; i++)
                #pragma unroll
                for (int j = 0; j < 4; j++) {
                    const int jh = j >> 1, sel = j & 1;
                    mma16f(acc[i][j], af[i], wfr[jh][sel], wfr[jh][sel + 2]);
                }
        }
        if (kc + 1 < 8) {
            cp_wait<0>();
            __syncthreads();
        }
    }

    if (z != 2) {
        const float post = (z == 0) ? 0.0625f : 1.0f;
        uint32_t* o = (z == 0) ? g_qh : g_kh;
        #pragma unroll
        for (int i = 0; i < 4; i++)
            #pragma unroll
            for (int j = 0; j < 4; j++) {
                const int c  = n0 + wn + j*8 + 2*tg;
                const int h  = c >> 6, hd = c & 63;
                const float b0 = bias[c], b1 = bias[c + 1];
                #pragma unroll
                for (int rr = 0; rr < 2; rr++) {
                    const int m  = m0 + wm + i*16 + g + rr*8;
                    const int b_ = m >> 11, s = m & 2047;
                    const float f0 = (acc[i][j][rr*2+0] * 0.015625f + b0) * post;
                    const float f1 = (acc[i][j][rr*2+1] * 0.015625f + b1) * post;
                    o[(((size_t)(b_ * Hv + h)) * Sv + s) * 32 + (hd >> 1)] = pack_f16(f0, f1);
                }
            }
    } else {
        // V epilogue: smem transpose [hd-local 128][stride 130] of m-local 128
        float* smf = (float*)su;       // 128*130 = 16640 floats <= 18432 u32
        __syncthreads();
        #pragma unroll
        for (int i = 0; i < 4; i++)
            #pragma unroll
            for (int j = 0; j < 4; j++) {
                const int hl = wn + j*8 + 2*tg;
                const int c  = n0 + hl;
                const float b0 = bias[c], b1 = bias[c + 1];
                #pragma unroll
                for (int rr = 0; rr < 2; rr++) {
                    const int ml = wm + i*16 + g + rr*8;
                    smf[hl * 130 + ml]       = acc[i][j][rr*2+0] * 0.015625f + b0;
                    smf[(hl + 1) * 130 + ml] = acc[i][j][rr*2+1] * 0.015625f + b1;
                }
            }
        __syncthreads();
        const int b_ = m0 >> 11, s0 = m0 & 2047;
        #pragma unroll
        for (int u = 0; u < 32; u++) {
            const int o  = u * 256 + tid;
            const int hl = o >> 6;                      // 0..127
            const int sp = o & 63;                      // s-pair within 128-row tile
            const int head = (n0 + hl) >> 6, hd = (n0 + hl) & 63;
            g_vt[(((size_t)(b_ * Hv + head)) * HDv + hd) * (Sv/2) + (s0 >> 1) + sp] =
                pack_f16(smf[hl * 130 + 2*sp], smf[hl * 130 + 2*sp + 1]);
        }
    }
}

// ---------------------------------------------------------------------------
// Kernel 2: fused sigmoid attention (exact round-14 version).
// 128 thr, 4 warps = 2 row-groups x 2 KV-halves, 4 blocks/SM.
// smem u32 (stride 36): Qh 0 (2304), Kh 2304 + buf*2304, Vt 6912 + buf*2304.
// Total 11520 u32 = 46080 B.
// ---------------------------------------------------------------------------
__global__ __launch_bounds__(128, 4) void attn_mma(float* __restrict__ out)
{
    extern __shared__ uint32_t su[];
    const uint32_t sb = smem_u32(su);
    const int tid = threadIdx.x, wid = tid >> 5, lane = tid & 31;
    const int g = lane >> 2, tg = lane & 3;
    const int lrow = lane & 15;
    const uint32_t lhi = (uint32_t)(lane >> 4) * 16u;
    const int wm = (wid >> 1) * 32;      // row group (0 or 32)
    const int wc = wid & 1;              // KV half
    const int qt = blockIdx.x, bh = blockIdx.y;

    const uint32_t* Qhg = g_qh + ((size_t)bh * Sv + (size_t)qt * 64) * 32;
    const uint32_t* Khg = g_kh + (size_t)bh * Sv * 32;
    const uint32_t* Vtg = g_vt + (size_t)bh * HDv * (Sv/2);

    float acc2[2][8][4] = {};

    stage_u<64,32,36,128>(sb,           Qhg, 32);
    stage_u<64,32,36,128>(sb + 2304*4,  Khg, 32);
    stage_u<64,32,36,128>(sb + 6912*4,  Vtg, Sv/2);
    cp_commit();
    cp_wait<0>();
    __syncthreads();

    const uint32_t qaddr = sb + (uint32_t)((wm + lrow) * 36) * 4 + lhi;
    const uint32_t kaddr = sb + 2304u*4u + (uint32_t)((wc*32 + lrow) * 36) * 4 + lhi;
    const uint32_t vaddr = sb + 6912u*4u + (uint32_t)(lrow * 36) * 4
                         + (uint32_t)wc * 64u + lhi;

    const int NT = Sv / 64;   // 32
    #pragma unroll 1
    for (int t = 0; t < NT; t++) {
        if (t + 1 < NT) {
            const uint32_t bo = ((t + 1) & 1) * 2304u * 4u;
            stage_u<64,32,36,128>(sb + 2304*4 + bo, Khg + (size_t)(t+1) * 64 * 32, 32);
            stage_u<64,32,36,128>(sb + 6912*4 + bo, Vtg + (size_t)(t+1) * 32,      Sv/2);
            cp_commit();
        }
        const uint32_t kb_t = kaddr + (uint32_t)(t & 1) * (2304u*4u);
        const uint32_t vb_t = vaddr + (uint32_t)(t & 1) * (2304u*4u);

        // ---- GEMM1 both 16-KV chunks of this warp's 32-KV half
        float acc1[2][2][2][4] = {};   // [kc][i][j]
        #pragma unroll
        for (int ks = 0; ks < 4; ks++) {
            const uint32_t ko = (uint32_t)ks * 32u;
            uint32_t qa[2][4], kb0[4], kb1[4];
            #pragma unroll
            for (int i = 0; i < 2; i++)
                ldsm4(qa[i], qaddr + (uint32_t)i * (16*144) + ko);
            ldsm4(kb0, kb_t + ko);
            ldsm4(kb1, kb_t + (16*144) + ko);
            #pragma unroll
            for (int i = 0; i < 2; i++) {
                mma16f(acc1[0][i][0], qa[i], kb0[0], kb0[2]);
                mma16f(acc1[0][i][1], qa[i], kb0[1], kb0[3]);
                mma16f(acc1[1][i][0], qa[i], kb1[0], kb1[2]);
                mma16f(acc1[1][i][1], qa[i], kb1[1], kb1[3]);
            }
        }

        // ---- sigmoid via tanh.approx.f16x2 -> fp16 A fragments
        uint32_t pa[2][2][4];          // [kc][i]
        #pragma unroll
        for (int kc = 0; kc < 2; kc++)
            #pragma unroll
            for (int i = 0; i < 2; i++) {
                pa[kc][i][0] = sigt(acc1[kc][i][0][0], acc1[kc][i][0][1]);
                pa[kc][i][1] = sigt(acc1[kc][i][0][2], acc1[kc][i][0][3]);
                pa[kc][i][2] = sigt(acc1[kc][i][1][0], acc1[kc][i][1][1]);
                pa[kc][i][3] = sigt(acc1[kc][i][1][2], acc1[kc][i][1][3]);
            }

        // ---- GEMM2 both chunks
        #pragma unroll
        for (int kc = 0; kc < 2; kc++)
            #pragma unroll
            for (int vq = 0; vq < 4; vq++) {
                uint32_t vb[4];
                ldsm4(vb, vb_t + (uint32_t)(vq * 16 * 144) + (uint32_t)kc * 32u);
                #pragma unroll
                for (int i = 0; i < 2; i++) {
                    mma16f(acc2[i][vq*2+0], pa[kc][i], vb[0], vb[2]);
                    mma16f(acc2[i][vq*2+1], pa[kc][i], vb[1], vb[3]);
                }
            }

        if (t + 1 < NT) {
            cp_wait<0>();
            __syncthreads();
        }
    }

    // ---- 2-way cross-warp O reduction (smem reuses dead operand tiles)
    float* smf = (float*)su;                   // 64 x 68 floats = 4352 < 11520
    __syncthreads();
    if (wc == 1) {
        #pragma unroll
        for (int i = 0; i < 2; i++)
            #pragma unroll
            for (int j2 = 0; j2 < 8; j2++)
                #pragma unroll
                for (int rr = 0; rr < 2; rr++) {
                    const int r = wm + i*16 + g + rr*8;
                    *(float2*)&smf[r * 68 + j2*8 + 2*tg] =
                        make_float2(acc2[i][j2][rr*2+0], acc2[i][j2][rr*2+1]);
                }
    }
    __syncthreads();
    if (wc == 0) {
        const int b_ = bh >> 3, h = bh & 7;
        #pragma unroll
        for (int i = 0; i < 2; i++)
            #pragma unroll
            for (int j2 = 0; j2 < 8; j2++)
                #pragma unroll
                for (int rr = 0; rr < 2; rr++) {
                    const int r = wm + i*16 + g + rr*8;
                    float2 v = *(const float2*)&smf[r * 68 + j2*8 + 2*tg];
                    v.x += acc2[i][j2][rr*2+0];
                    v.y += acc2[i][j2][rr*2+1];
                    const int s = qt * 64 + r;
                    *(float2*)&out[((size_t)(b_ * Sv + s)) * Dv + h * HDv + j2*8 + 2*tg] = v;
                }
    }
}

// ---------------------------------------------------------------------------
extern "C" void kernel_launch(void* const* d_in, const int* in_sizes, int n_in,
                              void* d_out, int out_size)
{
    const float* x  = (const float*)d_in[0];
    const float* wq = (const float*)d_in[1];
    const float* bq = (const float*)d_in[2];
    const float* wk = (const float*)d_in[3];
    const float* bk = (const float*)d_in[4];
    const float* wv = (const float*)d_in[5];
    const float* bv = (const float*)d_in[6];
    float* out = (float*)d_out;

    const int proj_smem = 18432 * 4;    // 73728 B
    const int attn_smem = 11520 * 4;    // 46080 B
    cudaFuncSetAttribute(proj_mma, cudaFuncAttributeMaxDynamicSharedMemorySize, proj_smem);
    cudaFuncSetAttribute(attn_mma, cudaFuncAttributeMaxDynamicSharedMemorySize, attn_smem);

    prep_xw<<<704, 256>>>(x, wq, wk, wv);

    dim3 g1((Bv * Sv) / 128, Dv / 128, 3);
    proj_mma<<<g1, 256, proj_smem>>>(bq, bk, bv);

    dim3 g3(Sv / 64, BH);
    attn_mma<<<g3, 128, attn_smem>>>(out);
}

// round 17
// speedup vs baseline: 1.0311x; 1.0168x over previous
#include <cuda_runtime.h>
#include <cuda_fp16.h>
#include <cstdint>

#define Bv  2
#define Sv  2048
#define Dv  512
#define Hv  8
#define HDv 64
#define BH  16

// Scratch (allocation-free __device__ globals)
__device__ uint32_t g_xf[4096*256];                     // x fp16 pairs along D
__device__ uint32_t g_wf[3*512*256];                    // (64*w) fp16 pairs
__device__ uint32_t g_qh[BH*Sv*32];                     // (Q/16) fp16 pairs along HD
__device__ uint32_t g_kh[BH*Sv*32];                     // K fp16 pairs along HD
__device__ uint32_t g_vt[BH*HDv*(Sv/2)];                // Vt fp16 pairs along S

// ---------------------------------------------------------------------------
// helpers
// ---------------------------------------------------------------------------
__device__ __forceinline__ uint32_t smem_u32(const void* p) {
    uint32_t a;
    asm("{ .reg .u64 t; cvta.to.shared.u64 t, %1; cvt.u32.u64 %0, t; }"
        : "=r"(a) : "l"(p));
    return a;
}
__device__ __forceinline__ void cp16(uint32_t dst, const void* src) {
    asm volatile("cp.async.cg.shared.global [%0], [%1], 16;" :: "r"(dst), "l"(src) : "memory");
}
__device__ __forceinline__ void cp_commit() { asm volatile("cp.async.commit_group;" ::: "memory"); }
template<int N>
__device__ __forceinline__ void cp_wait() { asm volatile("cp.async.wait_group %0;" :: "n"(N) : "memory"); }

__device__ __forceinline__ void grid_dep_sync() {
    asm volatile("griddepcontrol.wait;" ::: "memory");
}
__device__ __forceinline__ void grid_dep_trigger() {
    asm volatile("griddepcontrol.launch_dependents;" ::: "memory");
}

__device__ __forceinline__ void ldsm4(uint32_t* r, uint32_t addr) {
    asm volatile("ldmatrix.sync.aligned.m8n8.x4.shared.b16 {%0,%1,%2,%3}, [%4];"
                 : "=r"(r[0]), "=r"(r[1]), "=r"(r[2]), "=r"(r[3]) : "r"(addr));
}

// fp16 m16n8k16, scalar b operands
__device__ __forceinline__ void mma16f(float* d, const uint32_t* a, uint32_t b0, uint32_t b1) {
    asm volatile(
        "mma.sync.aligned.m16n8k16.row.col.f32.f16.f16.f32 "
        "{%0,%1,%2,%3}, {%4,%5,%6,%7}, {%8,%9}, {%0,%1,%2,%3};"
        : "+f"(d[0]), "+f"(d[1]), "+f"(d[2]), "+f"(d[3])
        : "r"(a[0]), "r"(a[1]), "r"(a[2]), "r"(a[3]), "r"(b0), "r"(b1));
}

__device__ __forceinline__ uint32_t pack_f16(float f0, float f1) {
    uint32_t h;
    asm("cvt.rn.f16x2.f32 %0, %1, %2;" : "=r"(h) : "f"(f1), "f"(f0));
    return h;
}

// sigmoid of a pair via tanh.approx.f16x2 (accumulators already = z/2):
//   sigmoid(z) = 0.5*tanh(z/2) + 0.5
__device__ __forceinline__ uint32_t sigt(float f0, float f1) {
    uint32_t p = pack_f16(f0, f1);
    uint32_t t, r;
    asm("tanh.approx.f16x2 %0, %1;" : "=r"(t) : "r"(p));
    const uint32_t hlf = 0x38003800u;   // (0.5, 0.5) fp16x2
    asm("fma.rn.f16x2 %0, %1, %2, %3;" : "=r"(r) : "r"(t), "r"(hlf), "r"(hlf));
    return r;
}

// u32 tile stage: R rows x C u32 cols, smem row stride ST u32, gmem stride ld u32
template<int R, int C, int ST, int NT>
__device__ __forceinline__ void stage_u(uint32_t dst, const uint32_t* src, int ld) {
    constexpr int G = C / 4;
    #pragma unroll
    for (int u = 0; u < (R * G) / NT; u++) {
        const int e = u * NT + threadIdx.x;
        const int r = e / G, g = e % G;
        cp16(dst + (uint32_t)(r * ST + g * 4) * 4, src + (size_t)r * ld + g * 4);
    }
}

// ---------------------------------------------------------------------------
// Kernel 0: x -> fp16 pairs;  w*64 -> fp16 pairs.  2x float4 per thread.
// ---------------------------------------------------------------------------
__global__ __launch_bounds__(256) void prep_xw(
    const float* __restrict__ x,  const float* __restrict__ wq,
    const float* __restrict__ wk, const float* __restrict__ wv)
{
    const uint32_t XN4 = 4096u * 128u;
    const uint32_t WN4 = 512u * 128u;
    const uint32_t HALF = (XN4 + 3u * WN4) / 2u;   // 360448
    #pragma unroll
    for (int u = 0; u < 2; u++) {
        const uint32_t i = blockIdx.x * 256u + threadIdx.x + (uint32_t)u * HALF;
        if (i < XN4) {
            float4 f = ((const float4*)x)[i];
            uint2 o = make_uint2(pack_f16(f.x, f.y), pack_f16(f.z, f.w));
            ((uint2*)g_xf)[i] = o;
        } else {
            const uint32_t j = i - XN4;
            const float* w = (j < WN4) ? wq : (j < 2u*WN4) ? wk : wv;
            float4 f = ((const float4*)w)[j % WN4];
            uint2 o = make_uint2(pack_f16(f.x * 64.0f, f.y * 64.0f),
                                 pack_f16(f.z * 64.0f, f.w * 64.0f));
            ((uint2*)g_wf)[j] = o;
        }
    }
}

// ---------------------------------------------------------------------------
// Kernel 1: QKV projection, single-term fp16 (round-16 version) + PDL.
// 128x128 block tile, 256 thr, 8 warps (2x4), warp 64x32, 2 blocks/SM.
// ---------------------------------------------------------------------------
__global__ __launch_bounds__(256, 2) void proj_mma(
    const float* __restrict__ bq, const float* __restrict__ bk,
    const float* __restrict__ bv)
{
    extern __shared__ uint32_t su[];
    const uint32_t sb = smem_u32(su);
    const int tid = threadIdx.x, wid = tid >> 5, lane = tid & 31;
    const int g = lane >> 2, tg = lane & 3;
    const int lrow = lane & 15;
    const uint32_t lhi = (uint32_t)(lane >> 4) * 16u;
    const int wm = (wid >> 2) * 64, wn = (wid & 3) * 32;
    const int m0 = blockIdx.x * 128, n0 = blockIdx.y * 128;
    const int z  = blockIdx.z;
    const float* bias = (z == 0) ? bq : (z == 1) ? bk : bv;

    grid_dep_sync();   // wait for prep_xw output

    const uint32_t* Xf_g = g_xf + (size_t)m0 * 256;
    const uint32_t* Wf_g = g_wf + ((size_t)z * 512 + n0) * 256;

    const uint32_t ax  = sb + (uint32_t)((wm + lrow) * 36) * 4 + lhi;
    const uint32_t awf = sb + 4608u*4u + (uint32_t)((wn + lrow) * 36) * 4 + lhi;

    float acc[4][4][4] = {};

    stage_u<128,32,36,256>(sb,           Xf_g, 256);
    stage_u<128,32,36,256>(sb + 4608*4,  Wf_g, 256);
    cp_commit();
    cp_wait<0>();
    __syncthreads();

    #pragma unroll 1
    for (int kc = 0; kc < 8; kc++) {
        if (kc + 1 < 8) {
            const uint32_t bo = ((kc + 1) & 1) * 9216u * 4u;
            const int co = (kc + 1) * 32;
            stage_u<128,32,36,256>(sb + bo,           Xf_g + co, 256);
            stage_u<128,32,36,256>(sb + bo + 4608*4,  Wf_g + co, 256);
            cp_commit();
        }
        const uint32_t bo = (kc & 1) * 9216u * 4u;

        #pragma unroll
        for (int ks = 0; ks < 4; ks++) {
            const uint32_t ko = (uint32_t)ks * 32u;
            uint32_t af[4][4], wfr[2][4];
            #pragma unroll
            for (int i = 0; i < 4; i++)
                ldsm4(af[i], ax + bo + (uint32_t)i * (16*144) + ko);
            #pragma unroll
            for (int jh = 0; jh < 2; jh++)
                ldsm4(wfr[jh], awf + bo + (uint32_t)jh * (16*144) + ko);
            #pragma unroll
            for (int i = 0; i < 4; i++)
                #pragma unroll
                for (int j = 0; j < 4; j++) {
                    const int jh = j >> 1, sel = j & 1;
                    mma16f(acc[i][j], af[i], wfr[jh][sel], wfr[jh][sel + 2]);
                }
        }
        if (kc + 1 < 8) {
            cp_wait<0>();
            __syncthreads();
        }
    }

    grid_dep_trigger();   // mainloop done: let attn's grid launch/prologue overlap

    if (z != 2) {
        const float post = (z == 0) ? 0.0625f : 1.0f;
        uint32_t* o = (z == 0) ? g_qh : g_kh;
        #pragma unroll
        for (int i = 0; i < 4; i++)
            #pragma unroll
            for (int j = 0; j < 4; j++) {
                const int c  = n0 + wn + j*8 + 2*tg;
                const int h  = c >> 6, hd = c & 63;
                const float b0 = bias[c], b1 = bias[c + 1];
                #pragma unroll
                for (int rr = 0; rr < 2; rr++) {
                    const int m  = m0 + wm + i*16 + g + rr*8;
                    const int b_ = m >> 11, s = m & 2047;
                    const float f0 = (acc[i][j][rr*2+0] * 0.015625f + b0) * post;
                    const float f1 = (acc[i][j][rr*2+1] * 0.015625f + b1) * post;
                    o[(((size_t)(b_ * Hv + h)) * Sv + s) * 32 + (hd >> 1)] = pack_f16(f0, f1);
                }
            }
    } else {
        // V epilogue: smem transpose [hd-local 128][stride 130]
        float* smf = (float*)su;       // 128*130 = 16640 floats <= 18432 u32
        __syncthreads();
        #pragma unroll
        for (int i = 0; i < 4; i++)
            #pragma unroll
            for (int j = 0; j < 4; j++) {
                const int hl = wn + j*8 + 2*tg;
                const int c  = n0 + hl;
                const float b0 = bias[c], b1 = bias[c + 1];
                #pragma unroll
                for (int rr = 0; rr < 2; rr++) {
                    const int ml = wm + i*16 + g + rr*8;
                    smf[hl * 130 + ml]       = acc[i][j][rr*2+0] * 0.015625f + b0;
                    smf[(hl + 1) * 130 + ml] = acc[i][j][rr*2+1] * 0.015625f + b1;
                }
            }
        __syncthreads();
        const int b_ = m0 >> 11, s0 = m0 & 2047;
        #pragma unroll
        for (int u = 0; u < 32; u++) {
            const int o  = u * 256 + tid;
            const int hl = o >> 6;
            const int sp = o & 63;
            const int head = (n0 + hl) >> 6, hd = (n0 + hl) & 63;
            g_vt[(((size_t)(b_ * Hv + head)) * HDv + hd) * (Sv/2) + (s0 >> 1) + sp] =
                pack_f16(smf[hl * 130 + 2*sp], smf[hl * 130 + 2*sp + 1]);
        }
    }
}

// ---------------------------------------------------------------------------
// Kernel 2: fused sigmoid attention (round-14/16 version) + PDL entry sync.
// 128 thr, 4 warps = 2 row-groups x 2 KV-halves, 4 blocks/SM.
// ---------------------------------------------------------------------------
__global__ __launch_bounds__(128, 4) void attn_mma(float* __restrict__ out)
{
    extern __shared__ uint32_t su[];
    const uint32_t sb = smem_u32(su);
    const int tid = threadIdx.x, wid = tid >> 5, lane = tid & 31;
    const int g = lane >> 2, tg = lane & 3;
    const int lrow = lane & 15;
    const uint32_t lhi = (uint32_t)(lane >> 4) * 16u;
    const int wm = (wid >> 1) * 32;      // row group (0 or 32)
    const int wc = wid & 1;              // KV half
    const int qt = blockIdx.x, bh = blockIdx.y;

    const uint32_t* Qhg = g_qh + ((size_t)bh * Sv + (size_t)qt * 64) * 32;
    const uint32_t* Khg = g_kh + (size_t)bh * Sv * 32;
    const uint32_t* Vtg = g_vt + (size_t)bh * HDv * (Sv/2);

    const uint32_t qaddr = sb + (uint32_t)((wm + lrow) * 36) * 4 + lhi;
    const uint32_t kaddr = sb + 2304u*4u + (uint32_t)((wc*32 + lrow) * 36) * 4 + lhi;
    const uint32_t vaddr = sb + 6912u*4u + (uint32_t)(lrow * 36) * 4
                         + (uint32_t)wc * 64u + lhi;

    grid_dep_sync();   // wait for proj output before first cp.async

    float acc2[2][8][4] = {};

    stage_u<64,32,36,128>(sb,           Qhg, 32);
    stage_u<64,32,36,128>(sb + 2304*4,  Khg, 32);
    stage_u<64,32,36,128>(sb + 6912*4,  Vtg, Sv/2);
    cp_commit();
    cp_wait<0>();
    __syncthreads();

    const int NT = Sv / 64;   // 32
    #pragma unroll 1
    for (int t = 0; t < NT; t++) {
        if (t + 1 < NT) {
            const uint32_t bo = ((t + 1) & 1) * 2304u * 4u;
            stage_u<64,32,36,128>(sb + 2304*4 + bo, Khg + (size_t)(t+1) * 64 * 32, 32);
            stage_u<64,32,36,128>(sb + 6912*4 + bo, Vtg + (size_t)(t+1) * 32,      Sv/2);
            cp_commit();
        }
        const uint32_t kb_t = kaddr + (uint32_t)(t & 1) * (2304u*4u);
        const uint32_t vb_t = vaddr + (uint32_t)(t & 1) * (2304u*4u);

        // ---- GEMM1 both 16-KV chunks of this warp's 32-KV half
        float acc1[2][2][2][4] = {};   // [kc][i][j]
        #pragma unroll
        for (int ks = 0; ks < 4; ks++) {
            const uint32_t ko = (uint32_t)ks * 32u;
            uint32_t qa[2][4], kb0[4], kb1[4];
            #pragma unroll
            for (int i = 0; i < 2; i++)
                ldsm4(qa[i], qaddr + (uint32_t)i * (16*144) + ko);
            ldsm4(kb0, kb_t + ko);
            ldsm4(kb1, kb_t + (16*144) + ko);
            #pragma unroll
            for (int i = 0; i < 2; i++) {
                mma16f(acc1[0][i][0], qa[i], kb0[0], kb0[2]);
                mma16f(acc1[0][i][1], qa[i], kb0[1], kb0[3]);
                mma16f(acc1[1][i][0], qa[i], kb1[0], kb1[2]);
                mma16f(acc1[1][i][1], qa[i], kb1[1], kb1[3]);
            }
        }

        // ---- sigmoid via tanh.approx.f16x2 -> fp16 A fragments
        uint32_t pa[2][2][4];          // [kc][i]
        #pragma unroll
        for (int kc = 0; kc < 2; kc++)
            #pragma unroll
            for (int i = 0; i < 2; i++) {
                pa[kc][i][0] = sigt(acc1[kc][i][0][0], acc1[kc][i][0][1]);
                pa[kc][i][1] = sigt(acc1[kc][i][0][2], acc1[kc][i][0][3]);
                pa[kc][i][2] = sigt(acc1[kc][i][1][0], acc1[kc][i][1][1]);
                pa[kc][i][3] = sigt(acc1[kc][i][1][2], acc1[kc][i][1][3]);
            }

        // ---- GEMM2 both chunks
        #pragma unroll
        for (int kc = 0; kc < 2; kc++)
            #pragma unroll
            for (int vq = 0; vq < 4; vq++) {
                uint32_t vb[4];
                ldsm4(vb, vb_t + (uint32_t)(vq * 16 * 144) + (uint32_t)kc * 32u);
                #pragma unroll
                for (int i = 0; i < 2; i++) {
                    mma16f(acc2[i][vq*2+0], pa[kc][i], vb[0], vb[2]);
                    mma16f(acc2[i][vq*2+1], pa[kc][i], vb[1], vb[3]);
                }
            }

        if (t + 1 < NT) {
            cp_wait<0>();
            __syncthreads();
        }
    }

    // ---- 2-way cross-warp O reduction (smem reuses dead operand tiles)
    float* smf = (float*)su;                   // 64 x 68 floats = 4352 < 11520
    __syncthreads();
    if (wc == 1) {
        #pragma unroll
        for (int i = 0; i < 2; i++)
            #pragma unroll
            for (int j2 = 0; j2 < 8; j2++)
                #pragma unroll
                for (int rr = 0; rr < 2; rr++) {
                    const int r = wm + i*16 + g + rr*8;
                    *(float2*)&smf[r * 68 + j2*8 + 2*tg] =
                        make_float2(acc2[i][j2][rr*2+0], acc2[i][j2][rr*2+1]);
                }
    }
    __syncthreads();
    if (wc == 0) {
        const int b_ = bh >> 3, h = bh & 7;
        #pragma unroll
        for (int i = 0; i < 2; i++)
            #pragma unroll
            for (int j2 = 0; j2 < 8; j2++)
                #pragma unroll
                for (int rr = 0; rr < 2; rr++) {
                    const int r = wm + i*16 + g + rr*8;
                    float2 v = *(const float2*)&smf[r * 68 + j2*8 + 2*tg];
                    v.x += acc2[i][j2][rr*2+0];
                    v.y += acc2[i][j2][rr*2+1];
                    const int s = qt * 64 + r;
                    *(float2*)&out[((size_t)(b_ * Sv + s)) * Dv + h * HDv + j2*8 + 2*tg] = v;
                }
    }
}

// ---------------------------------------------------------------------------
extern "C" void kernel_launch(void* const* d_in, const int* in_sizes, int n_in,
                              void* d_out, int out_size)
{
    const float* x  = (const float*)d_in[0];
    const float* wq = (const float*)d_in[1];
    const float* bq = (const float*)d_in[2];
    const float* wk = (const float*)d_in[3];
    const float* bk = (const float*)d_in[4];
    const float* wv = (const float*)d_in[5];
    const float* bv = (const float*)d_in[6];
    float* out = (float*)d_out;

    const int proj_smem = 18432 * 4;    // 73728 B
    const int attn_smem = 11520 * 4;    // 46080 B
    cudaFuncSetAttribute(proj_mma, cudaFuncAttributeMaxDynamicSharedMemorySize, proj_smem);
    cudaFuncSetAttribute(attn_mma, cudaFuncAttributeMaxDynamicSharedMemorySize, attn_smem);

    prep_xw<<<1408, 256>>>(x, wq, wk, wv);

    // proj with PDL (overlaps its launch with prep's tail)
    {
        cudaLaunchConfig_t cfg = {};
        cfg.gridDim  = dim3((Bv * Sv) / 128, Dv / 128, 3);
        cfg.blockDim = dim3(256, 1, 1);
        cfg.dynamicSmemBytes = proj_smem;
        cudaLaunchAttribute at[1];
        at[0].id = cudaLaunchAttributeProgrammaticStreamSerialization;
        at[0].val.programmaticStreamSerializationAllowed = 1;
        cfg.attrs = at;
        cfg.numAttrs = 1;
        cudaLaunchKernelEx(&cfg, proj_mma, bq, bk, bv);
    }

    // attn with PDL (launch/prologue overlaps proj's epilogue)
    {
        cudaLaunchConfig_t cfg = {};
        cfg.gridDim  = dim3(Sv / 64, BH, 1);
        cfg.blockDim = dim3(128, 1, 1);
        cfg.dynamicSmemBytes = attn_smem;
        cudaLaunchAttribute at[1];
        at[0].id = cudaLaunchAttributeProgrammaticStreamSerialization;
        at[0].val.programmaticStreamSerializationAllowed = 1;
        cfg.attrs = at;
        cfg.numAttrs = 1;
        cudaLaunchKernelEx(&cfg, attn_mma, out);
    }
}